// round 1
// baseline (speedup 1.0000x reference)
#include <cuda_runtime.h>
#include <math.h>

#define BB 8
#define LL 4096
#define DD 1024
#define MM (BB * LL)          // 32768 rows
#define DD2 (2 * DD)          // 2048
#define NCH 32
#define CHUNK (LL / NCH)      // 128

// ---------------- scratch (device globals; no allocation allowed) ----------
__device__ float g_avg[(size_t)MM * DD];      // cumulative mean          128 MB
__device__ float g_h[(size_t)MM * DD];        // layernorm(avg)           128 MB
__device__ float g_inter[(size_t)MM * DD];    // relu(h@w1+b1)            128 MB
__device__ float g_avgout[(size_t)MM * DD];   // inter@w2+b2+avg          128 MB
__device__ float g_gates[(size_t)MM * DD2];   // concat@wg+bg             256 MB
__device__ float g_csum[BB * NCH * DD];       // chunk partial sums

// ---------------- phase 1: chunked cumulative sum --------------------------
__global__ void __launch_bounds__(256) k_chunksum(const float* __restrict__ in) {
    int idx = blockIdx.x * blockDim.x + threadIdx.x;   // B*NCH*D = 262144
    int d = idx & (DD - 1);
    int chunk = (idx >> 10) & (NCH - 1);
    int b = idx >> 15;
    const float* p = in + ((size_t)(b * LL + chunk * CHUNK)) * DD + d;
    float s = 0.f;
#pragma unroll 4
    for (int l = 0; l < CHUNK; ++l) s += p[(size_t)l * DD];
    g_csum[(b * NCH + chunk) * DD + d] = s;
}

__global__ void __launch_bounds__(256) k_scan() {
    int idx = blockIdx.x * blockDim.x + threadIdx.x;   // B*D = 8192
    int d = idx & (DD - 1);
    int b = idx >> 10;
    float run = 0.f;
#pragma unroll
    for (int c = 0; c < NCH; ++c) {
        int o = (b * NCH + c) * DD + d;
        float t = g_csum[o];
        g_csum[o] = run;                                // exclusive
        run += t;
    }
}

__global__ void __launch_bounds__(256) k_apply(const float* __restrict__ in) {
    int idx = blockIdx.x * blockDim.x + threadIdx.x;   // B*NCH*D
    int d = idx & (DD - 1);
    int chunk = (idx >> 10) & (NCH - 1);
    int b = idx >> 15;
    size_t base = ((size_t)(b * LL + chunk * CHUNK)) * DD + d;
    const float* p = in + base;
    float* q = g_avg + base;
    float run = g_csum[(b * NCH + chunk) * DD + d];
    int l0 = chunk * CHUNK;
#pragma unroll 4
    for (int l = 0; l < CHUNK; ++l) {
        run += p[(size_t)l * DD];
        q[(size_t)l * DD] = run / (float)(l0 + l + 1);
    }
}

// ---------------- phase 2: layernorm over D per row -------------------------
__global__ void __launch_bounds__(256) k_ln(const float* __restrict__ lng,
                                            const float* __restrict__ lnb) {
    int row = blockIdx.x;
    int t = threadIdx.x;
    const float4* x4 = reinterpret_cast<const float4*>(g_avg + (size_t)row * DD);
    float4 a = x4[t];                                   // D/4 = 256 = blockDim
    float s = a.x + a.y + a.z + a.w;
    float ss = a.x * a.x + a.y * a.y + a.z * a.z + a.w * a.w;
#pragma unroll
    for (int o = 16; o > 0; o >>= 1) {
        s  += __shfl_xor_sync(0xffffffffu, s, o);
        ss += __shfl_xor_sync(0xffffffffu, ss, o);
    }
    __shared__ float sm[16];
    int w = t >> 5;
    if ((t & 31) == 0) { sm[w] = s; sm[8 + w] = ss; }
    __syncthreads();
    if (t < 32) {
        float v1 = (t < 8) ? sm[t] : 0.f;
        float v2 = (t < 8) ? sm[8 + t] : 0.f;
#pragma unroll
        for (int o = 4; o > 0; o >>= 1) {
            v1 += __shfl_xor_sync(0xffffffffu, v1, o);
            v2 += __shfl_xor_sync(0xffffffffu, v2, o);
        }
        if (t == 0) { sm[0] = v1; sm[1] = v2; }
    }
    __syncthreads();
    float mean = sm[0] * (1.f / DD);
    float var  = sm[1] * (1.f / DD) - mean * mean;
    float inv  = rsqrtf(var + 1e-6f);
    float4 g = reinterpret_cast<const float4*>(lng)[t];
    float4 b = reinterpret_cast<const float4*>(lnb)[t];
    float4 h;
    h.x = (a.x - mean) * inv * g.x + b.x;
    h.y = (a.y - mean) * inv * g.y + b.y;
    h.z = (a.z - mean) * inv * g.z + b.z;
    h.w = (a.w - mean) * inv * g.w + b.w;
    reinterpret_cast<float4*>(g_h + (size_t)row * DD)[t] = h;
}

// ---------------- phase 3: SGEMM 128x128x8, 8x8 microtile -------------------
// C[M,NN] = A[M,KTOT] * W[KTOT,NN] (+epilogue). A row k<DD comes from A0,
// k>=DD from A1 (both have row stride DD) -> concat without materializing.
// MODE 0: relu(x + bias)      (gemm1 -> inter)
// MODE 1: x + bias + add[r,c] (gemm2 -> avg_out)
// MODE 2: x + bias            (gemm3 -> gates)
template <int MODE, int KTOT, int NN>
__global__ void __launch_bounds__(256) k_gemm(const float* __restrict__ A0,
                                              const float* __restrict__ A1,
                                              const float* __restrict__ W,
                                              const float* __restrict__ bias,
                                              const float* __restrict__ add,
                                              float* __restrict__ C) {
    constexpr int BM = 128, BN = 128, BK = 8;
    __shared__ float As[BK][BM];
    __shared__ float Bs[BK][BN];
    int tid = threadIdx.x;
    int bm = blockIdx.y * BM;
    int bn = blockIdx.x * BN;
    int aRow = tid >> 1;
    int aCol = (tid & 1) * 4;
    int bRow = tid >> 5;
    int bCol = (tid & 31) * 4;
    int ty = tid >> 4;        // 0..15 -> rows ty*8..ty*8+7
    int tx = tid & 15;        // 0..15 -> cols tx*8..tx*8+7

    float acc[8][8];
#pragma unroll
    for (int i = 0; i < 8; ++i)
#pragma unroll
        for (int j = 0; j < 8; ++j) acc[i][j] = 0.f;

    for (int kk = 0; kk < KTOT; kk += BK) {
        int ka = kk + aCol;
        const float* asrc = (ka < DD)
            ? (A0 + (size_t)(bm + aRow) * DD + ka)
            : (A1 + (size_t)(bm + aRow) * DD + (ka - DD));
        float4 av = *reinterpret_cast<const float4*>(asrc);
        As[aCol + 0][aRow] = av.x;
        As[aCol + 1][aRow] = av.y;
        As[aCol + 2][aRow] = av.z;
        As[aCol + 3][aRow] = av.w;
        float4 bv = *reinterpret_cast<const float4*>(
            W + (size_t)(kk + bRow) * NN + bn + bCol);
        *reinterpret_cast<float4*>(&Bs[bRow][bCol]) = bv;
        __syncthreads();
#pragma unroll
        for (int k = 0; k < BK; ++k) {
            float ra[8], rb[8];
            *reinterpret_cast<float4*>(&ra[0]) =
                *reinterpret_cast<const float4*>(&As[k][ty * 8]);
            *reinterpret_cast<float4*>(&ra[4]) =
                *reinterpret_cast<const float4*>(&As[k][ty * 8 + 4]);
            *reinterpret_cast<float4*>(&rb[0]) =
                *reinterpret_cast<const float4*>(&Bs[k][tx * 8]);
            *reinterpret_cast<float4*>(&rb[4]) =
                *reinterpret_cast<const float4*>(&Bs[k][tx * 8 + 4]);
#pragma unroll
            for (int i = 0; i < 8; ++i)
#pragma unroll
                for (int j = 0; j < 8; ++j) acc[i][j] += ra[i] * rb[j];
        }
        __syncthreads();
    }

#pragma unroll
    for (int i = 0; i < 8; ++i) {
        int r = bm + ty * 8 + i;
        size_t base = (size_t)r * NN + bn + tx * 8;
#pragma unroll
        for (int jv = 0; jv < 2; ++jv) {
            float4 v;
            v.x = acc[i][jv * 4 + 0];
            v.y = acc[i][jv * 4 + 1];
            v.z = acc[i][jv * 4 + 2];
            v.w = acc[i][jv * 4 + 3];
            float4 bb = *reinterpret_cast<const float4*>(bias + bn + tx * 8 + jv * 4);
            v.x += bb.x; v.y += bb.y; v.z += bb.z; v.w += bb.w;
            if (MODE == 0) {
                v.x = fmaxf(v.x, 0.f); v.y = fmaxf(v.y, 0.f);
                v.z = fmaxf(v.z, 0.f); v.w = fmaxf(v.w, 0.f);
            }
            if (MODE == 1) {
                float4 ad = *reinterpret_cast<const float4*>(add + base + jv * 4);
                v.x += ad.x; v.y += ad.y; v.z += ad.z; v.w += ad.w;
            }
            *reinterpret_cast<float4*>(C + base + jv * 4) = v;
        }
    }
}

// ---------------- phase 4: gate combine --------------------------------------
__device__ __forceinline__ float sigf(float x) { return 1.f / (1.f + expf(-x)); }

__global__ void __launch_bounds__(256) k_final(const float* __restrict__ in,
                                               float* __restrict__ out) {
    int idx = blockIdx.x * blockDim.x + threadIdx.x;   // over M*D/4
    int row = idx >> 8;                                 // D/4 = 256
    int d4 = idx & 255;
    float4 i4 = reinterpret_cast<const float4*>(in)[idx];
    float4 a4 = reinterpret_cast<const float4*>(g_avgout)[idx];
    const float4* gr = reinterpret_cast<const float4*>(g_gates) + (size_t)row * 512;
    float4 g1 = gr[d4];
    float4 g2 = gr[256 + d4];
    float4 o;
    o.x = sigf(g1.x) * i4.x + sigf(g2.x) * a4.x;
    o.y = sigf(g1.y) * i4.y + sigf(g2.y) * a4.y;
    o.z = sigf(g1.z) * i4.z + sigf(g2.z) * a4.z;
    o.w = sigf(g1.w) * i4.w + sigf(g2.w) * a4.w;
    reinterpret_cast<float4*>(out)[idx] = o;
}

// ---------------- launch -----------------------------------------------------
extern "C" void kernel_launch(void* const* d_in, const int* in_sizes, int n_in,
                              void* d_out, int out_size) {
    const float* inputs = (const float*)d_in[0];
    const float* w1 = (const float*)d_in[1];
    const float* b1 = (const float*)d_in[2];
    const float* w2 = (const float*)d_in[3];
    const float* b2 = (const float*)d_in[4];
    const float* lng = (const float*)d_in[5];
    const float* lnb = (const float*)d_in[6];
    const float* wg = (const float*)d_in[7];
    const float* bg = (const float*)d_in[8];
    float* out = (float*)d_out;

    float *avg, *h, *inter, *avgout, *gates;
    cudaGetSymbolAddress((void**)&avg, g_avg);
    cudaGetSymbolAddress((void**)&h, g_h);
    cudaGetSymbolAddress((void**)&inter, g_inter);
    cudaGetSymbolAddress((void**)&avgout, g_avgout);
    cudaGetSymbolAddress((void**)&gates, g_gates);

    k_chunksum<<<(BB * NCH * DD) / 256, 256>>>(inputs);
    k_scan<<<(BB * DD) / 256, 256>>>();
    k_apply<<<(BB * NCH * DD) / 256, 256>>>(inputs);
    k_ln<<<MM, 256>>>(lng, lnb);

    dim3 grid12(DD / 128, MM / 128);    // (8, 256)
    k_gemm<0, DD, DD><<<grid12, 256>>>(h, h, w1, b1, nullptr, inter);
    k_gemm<1, DD, DD><<<grid12, 256>>>(inter, inter, w2, b2, avg, avgout);

    dim3 grid3(DD2 / 128, MM / 128);    // (16, 256)
    k_gemm<2, DD2, DD2><<<grid3, 256>>>(inputs, avgout, wg, bg, nullptr, gates);

    k_final<<<((size_t)MM * DD / 4) / 256, 256>>>(inputs, out);
}

// round 3
// speedup vs baseline: 3.6534x; 3.6534x over previous
#include <cuda_runtime.h>
#include <math.h>
#include <stdint.h>

#define BB 8
#define LL 4096
#define DD 1024
#define MM (BB * LL)          // 32768 rows
#define DD2 (2 * DD)          // 2048
#define NCH 32
#define CHUNK (LL / NCH)      // 128

// ---------------- scratch (device globals; no allocation allowed) ----------
__device__ float g_avg[(size_t)MM * DD];      // cumulative mean (full fp32)
__device__ float g_h[(size_t)MM * DD];        // layernorm(avg), tf32-rounded
__device__ float g_inter[(size_t)MM * DD];    // relu(h@w1+b1), tf32-rounded
__device__ float g_avgout[(size_t)MM * DD];   // inter@w2+b2+avg (full fp32)
__device__ float g_avgout_r[(size_t)MM * DD]; // tf32-rounded copy
__device__ float g_in_r[(size_t)MM * DD];     // tf32-rounded inputs
__device__ float g_gates[(size_t)MM * DD2];   // concat@wg+bg (full fp32)
__device__ float g_csum[BB * NCH * DD];       // chunk partial sums
__device__ float g_w1t[DD * DD];              // w1^T [N][K], tf32-rounded
__device__ float g_w2t[DD * DD];
__device__ float g_wgt[(size_t)DD2 * DD2];

// ---------------- helpers ----------------------------------------------------
__device__ __forceinline__ float f2tf32f(float x) {
    uint32_t r;
    asm("cvt.rna.tf32.f32 %0, %1;" : "=r"(r) : "f"(x));
    return __uint_as_float(r);
}

#define CP_ASYNC16(dst, src) \
    asm volatile("cp.async.cg.shared.global [%0], [%1], 16;" \
                 :: "r"(dst), "l"(src) : "memory")
#define CP_COMMIT() asm volatile("cp.async.commit_group;" ::: "memory")

// ---------------- phase 1: chunked cumulative sum --------------------------
__global__ void __launch_bounds__(256) k_chunksum(const float* __restrict__ in) {
    int idx = blockIdx.x * blockDim.x + threadIdx.x;
    int d = idx & (DD - 1);
    int chunk = (idx >> 10) & (NCH - 1);
    int b = idx >> 15;
    const float* p = in + ((size_t)(b * LL + chunk * CHUNK)) * DD + d;
    float s = 0.f;
#pragma unroll 4
    for (int l = 0; l < CHUNK; ++l) s += p[(size_t)l * DD];
    g_csum[(b * NCH + chunk) * DD + d] = s;
}

__global__ void __launch_bounds__(256) k_scan() {
    int idx = blockIdx.x * blockDim.x + threadIdx.x;
    int d = idx & (DD - 1);
    int b = idx >> 10;
    float run = 0.f;
#pragma unroll
    for (int c = 0; c < NCH; ++c) {
        int o = (b * NCH + c) * DD + d;
        float t = g_csum[o];
        g_csum[o] = run;
        run += t;
    }
}

__global__ void __launch_bounds__(256) k_apply(const float* __restrict__ in) {
    int idx = blockIdx.x * blockDim.x + threadIdx.x;
    int d = idx & (DD - 1);
    int chunk = (idx >> 10) & (NCH - 1);
    int b = idx >> 15;
    size_t base = ((size_t)(b * LL + chunk * CHUNK)) * DD + d;
    const float* p = in + base;
    float* q = g_avg + base;
    float* qr = g_in_r + base;
    float run = g_csum[(b * NCH + chunk) * DD + d];
    int l0 = chunk * CHUNK;
#pragma unroll 4
    for (int l = 0; l < CHUNK; ++l) {
        float v = p[(size_t)l * DD];
        run += v;
        q[(size_t)l * DD] = run / (float)(l0 + l + 1);
        qr[(size_t)l * DD] = f2tf32f(v);
    }
}

// ---------------- phase 2: layernorm over D per row (tf32-rounded out) ------
__global__ void __launch_bounds__(256) k_ln(const float* __restrict__ lng,
                                            const float* __restrict__ lnb) {
    int row = blockIdx.x;
    int t = threadIdx.x;
    const float4* x4 = reinterpret_cast<const float4*>(g_avg + (size_t)row * DD);
    float4 a = x4[t];
    float s = a.x + a.y + a.z + a.w;
    float ss = a.x * a.x + a.y * a.y + a.z * a.z + a.w * a.w;
#pragma unroll
    for (int o = 16; o > 0; o >>= 1) {
        s  += __shfl_xor_sync(0xffffffffu, s, o);
        ss += __shfl_xor_sync(0xffffffffu, ss, o);
    }
    __shared__ float sm[16];
    int w = t >> 5;
    if ((t & 31) == 0) { sm[w] = s; sm[8 + w] = ss; }
    __syncthreads();
    if (t < 32) {
        float v1 = (t < 8) ? sm[t] : 0.f;
        float v2 = (t < 8) ? sm[8 + t] : 0.f;
#pragma unroll
        for (int o = 4; o > 0; o >>= 1) {
            v1 += __shfl_xor_sync(0xffffffffu, v1, o);
            v2 += __shfl_xor_sync(0xffffffffu, v2, o);
        }
        if (t == 0) { sm[0] = v1; sm[1] = v2; }
    }
    __syncthreads();
    float mean = sm[0] * (1.f / DD);
    float var  = sm[1] * (1.f / DD) - mean * mean;
    float inv  = rsqrtf(var + 1e-6f);
    float4 g = reinterpret_cast<const float4*>(lng)[t];
    float4 b = reinterpret_cast<const float4*>(lnb)[t];
    float4 h;
    h.x = f2tf32f((a.x - mean) * inv * g.x + b.x);
    h.y = f2tf32f((a.y - mean) * inv * g.y + b.y);
    h.z = f2tf32f((a.z - mean) * inv * g.z + b.z);
    h.w = f2tf32f((a.w - mean) * inv * g.w + b.w);
    reinterpret_cast<float4*>(g_h + (size_t)row * DD)[t] = h;
}

// ---------------- weight transpose (tf32-rounded): Wt[n][k] = W[k][n] -------
__global__ void __launch_bounds__(256) k_transpose(const float* __restrict__ W,
                                                   float* __restrict__ Wt, int N) {
    __shared__ float t[32][33];
    int bx = blockIdx.x * 32, by = blockIdx.y * 32;
    int x = bx + threadIdx.x;
#pragma unroll
    for (int i = 0; i < 32; i += 8)
        t[threadIdx.y + i][threadIdx.x] = W[(size_t)(by + threadIdx.y + i) * N + x];
    __syncthreads();
    int x2 = by + threadIdx.x;
#pragma unroll
    for (int i = 0; i < 32; i += 8)
        Wt[(size_t)(bx + threadIdx.y + i) * N + x2] = f2tf32f(t[threadIdx.x][threadIdx.y + i]);
}

// ---------------- phase 3: tf32 mma.sync GEMM --------------------------------
// C[M,NN] = concatA[M,KTOT] @ Wt[NN,KTOT]^T, Wt K-major.
// CTA tile 128x128, BK=32, 8 warps (2x4), warp tile 64x32, mma m16n8k8.
// Smem rows padded to 36 floats: conflict-free fragment loads, 16B cp.async.
// MODE 0: round(relu(x+b))->C            (gemm1 -> inter)
// MODE 1: x+b+add->C, round(...)->C2     (gemm2 -> avgout, avgout_r)
// MODE 2: x+b->C                         (gemm3 -> gates)
#define LDP 36
#define STG_FLTS (2 * 128 * LDP)          // A tile + B tile per stage
#define GEMM_SMEM (2 * STG_FLTS * 4)      // 2 stages = 73728 B

template <int MODE, int KTOT, int NN>
__global__ void __launch_bounds__(256, 2) k_gemm_mma(
    const float* __restrict__ A0, const float* __restrict__ A1,
    const float* __restrict__ Wt, const float* __restrict__ bias,
    const float* __restrict__ add, float* __restrict__ C,
    float* __restrict__ C2) {
    extern __shared__ float smf[];
    int tid = threadIdx.x;
    int wid = tid >> 5, lane = tid & 31;
    int g = lane >> 2, tg = lane & 3;
    int wm = wid >> 2, wn = wid & 3;       // 2 x 4 warp grid
    int bm = blockIdx.y * 128, bn = blockIdx.x * 128;

    float acc[16][4];
#pragma unroll
    for (int i = 0; i < 16; ++i)
#pragma unroll
        for (int j = 0; j < 4; ++j) acc[i][j] = 0.f;

    // stage loader: A tile 128x32 + B tile 128x32 via cp.async 16B
    int ldr = tid >> 3;                    // 0..31 (row group)
    int ldc = (tid & 7) << 2;              // 0,4,...,28
    const int NK = KTOT / 32;

#define LOAD_STAGE(s, kk_)                                                     \
    {                                                                          \
        int kk = (kk_);                                                        \
        const float* Ab; int kloc;                                             \
        if (MODE == 2 && kk >= DD) { Ab = A1; kloc = kk - DD; }                \
        else                        { Ab = A0; kloc = kk; }                    \
        float* As = smf + (s) * STG_FLTS;                                      \
        float* Bs = As + 128 * LDP;                                            \
        _Pragma("unroll")                                                      \
        for (int it = 0; it < 4; ++it) {                                       \
            int r = ldr + it * 32;                                             \
            uint32_t da = (uint32_t)__cvta_generic_to_shared(As + r * LDP + ldc); \
            CP_ASYNC16(da, Ab + (size_t)(bm + r) * DD + kloc + ldc);           \
            uint32_t db = (uint32_t)__cvta_generic_to_shared(Bs + r * LDP + ldc); \
            CP_ASYNC16(db, Wt + (size_t)(bn + r) * KTOT + kk + ldc);           \
        }                                                                      \
    }

    LOAD_STAGE(0, 0);
    CP_COMMIT();

    for (int kt = 0; kt < NK; ++kt) {
        int cur = kt & 1;
        if (kt + 1 < NK) {
            LOAD_STAGE(cur ^ 1, (kt + 1) * 32);
            CP_COMMIT();
            asm volatile("cp.async.wait_group 1;" ::: "memory");
        } else {
            asm volatile("cp.async.wait_group 0;" ::: "memory");
        }
        __syncthreads();

        const float* As = smf + cur * STG_FLTS;
        const float* Bs = As + 128 * LDP;
#pragma unroll
        for (int kc = 0; kc < 4; ++kc) {
            int kb = kc * 8;
            uint32_t af[4][4], bf[4][2];
#pragma unroll
            for (int mt = 0; mt < 4; ++mt) {
                int r0 = (wm * 64 + mt * 16 + g) * LDP + kb + tg;
                af[mt][0] = __float_as_uint(As[r0]);
                af[mt][1] = __float_as_uint(As[r0 + 8 * LDP]);
                af[mt][2] = __float_as_uint(As[r0 + 4]);
                af[mt][3] = __float_as_uint(As[r0 + 8 * LDP + 4]);
            }
#pragma unroll
            for (int nt = 0; nt < 4; ++nt) {
                int r0 = (wn * 32 + nt * 8 + g) * LDP + kb + tg;
                bf[nt][0] = __float_as_uint(Bs[r0]);
                bf[nt][1] = __float_as_uint(Bs[r0 + 4]);
            }
#pragma unroll
            for (int mt = 0; mt < 4; ++mt)
#pragma unroll
                for (int nt = 0; nt < 4; ++nt) {
                    float* c = acc[mt * 4 + nt];
                    asm volatile(
                        "mma.sync.aligned.m16n8k8.row.col.f32.tf32.tf32.f32 "
                        "{%0,%1,%2,%3}, {%4,%5,%6,%7}, {%8,%9}, {%0,%1,%2,%3};"
                        : "+f"(c[0]), "+f"(c[1]), "+f"(c[2]), "+f"(c[3])
                        : "r"(af[mt][0]), "r"(af[mt][1]), "r"(af[mt][2]),
                          "r"(af[mt][3]), "r"(bf[nt][0]), "r"(bf[nt][1]));
                }
        }
        __syncthreads();
    }

    // epilogue
#pragma unroll
    for (int mt = 0; mt < 4; ++mt) {
#pragma unroll
        for (int nt = 0; nt < 4; ++nt) {
            float* c = acc[mt * 4 + nt];
            int col = bn + wn * 32 + nt * 8 + 2 * tg;
            float2 bb = *reinterpret_cast<const float2*>(bias + col);
#pragma unroll
            for (int hh = 0; hh < 2; ++hh) {
                int row = bm + wm * 64 + mt * 16 + g + hh * 8;
                size_t off = (size_t)row * NN + col;
                float vx = c[hh * 2 + 0] + bb.x;
                float vy = c[hh * 2 + 1] + bb.y;
                if (MODE == 0) {
                    float2 o;
                    o.x = f2tf32f(fmaxf(vx, 0.f));
                    o.y = f2tf32f(fmaxf(vy, 0.f));
                    *reinterpret_cast<float2*>(C + off) = o;
                } else if (MODE == 1) {
                    float2 ad = *reinterpret_cast<const float2*>(add + off);
                    vx += ad.x; vy += ad.y;
                    float2 o; o.x = vx; o.y = vy;
                    *reinterpret_cast<float2*>(C + off) = o;
                    float2 o2; o2.x = f2tf32f(vx); o2.y = f2tf32f(vy);
                    *reinterpret_cast<float2*>(C2 + off) = o2;
                } else {
                    float2 o; o.x = vx; o.y = vy;
                    *reinterpret_cast<float2*>(C + off) = o;
                }
            }
        }
    }
#undef LOAD_STAGE
}

// ---------------- phase 4: gate combine --------------------------------------
__device__ __forceinline__ float sigf(float x) { return 1.f / (1.f + expf(-x)); }

__global__ void __launch_bounds__(256) k_final(const float* __restrict__ in,
                                               float* __restrict__ out) {
    int idx = blockIdx.x * blockDim.x + threadIdx.x;
    int row = idx >> 8;
    int d4 = idx & 255;
    float4 i4 = reinterpret_cast<const float4*>(in)[idx];
    float4 a4 = reinterpret_cast<const float4*>(g_avgout)[idx];
    const float4* gr = reinterpret_cast<const float4*>(g_gates) + (size_t)row * 512;
    float4 g1 = gr[d4];
    float4 g2 = gr[256 + d4];
    float4 o;
    o.x = sigf(g1.x) * i4.x + sigf(g2.x) * a4.x;
    o.y = sigf(g1.y) * i4.y + sigf(g2.y) * a4.y;
    o.z = sigf(g1.z) * i4.z + sigf(g2.z) * a4.z;
    o.w = sigf(g1.w) * i4.w + sigf(g2.w) * a4.w;
    reinterpret_cast<float4*>(out)[idx] = o;
}

// ---------------- launch -----------------------------------------------------
extern "C" void kernel_launch(void* const* d_in, const int* in_sizes, int n_in,
                              void* d_out, int out_size) {
    const float* inputs = (const float*)d_in[0];
    const float* w1 = (const float*)d_in[1];
    const float* b1 = (const float*)d_in[2];
    const float* w2 = (const float*)d_in[3];
    const float* b2 = (const float*)d_in[4];
    const float* lng = (const float*)d_in[5];
    const float* lnb = (const float*)d_in[6];
    const float* wg = (const float*)d_in[7];
    const float* bg = (const float*)d_in[8];
    float* out = (float*)d_out;

    float *avg, *h, *inter, *avgout, *avgout_r, *in_r, *gates, *w1t, *w2t, *wgt;
    cudaGetSymbolAddress((void**)&avg, g_avg);
    cudaGetSymbolAddress((void**)&h, g_h);
    cudaGetSymbolAddress((void**)&inter, g_inter);
    cudaGetSymbolAddress((void**)&avgout, g_avgout);
    cudaGetSymbolAddress((void**)&avgout_r, g_avgout_r);
    cudaGetSymbolAddress((void**)&in_r, g_in_r);
    cudaGetSymbolAddress((void**)&gates, g_gates);
    cudaGetSymbolAddress((void**)&w1t, g_w1t);
    cudaGetSymbolAddress((void**)&w2t, g_w2t);
    cudaGetSymbolAddress((void**)&wgt, g_wgt);

    cudaFuncSetAttribute(k_gemm_mma<0, DD, DD>,
                         cudaFuncAttributeMaxDynamicSharedMemorySize, GEMM_SMEM);
    cudaFuncSetAttribute(k_gemm_mma<1, DD, DD>,
                         cudaFuncAttributeMaxDynamicSharedMemorySize, GEMM_SMEM);
    cudaFuncSetAttribute(k_gemm_mma<2, DD2, DD2>,
                         cudaFuncAttributeMaxDynamicSharedMemorySize, GEMM_SMEM);

    dim3 tb(32, 8);
    k_transpose<<<dim3(DD / 32, DD / 32), tb>>>(w1, w1t, DD);
    k_transpose<<<dim3(DD / 32, DD / 32), tb>>>(w2, w2t, DD);
    k_transpose<<<dim3(DD2 / 32, DD2 / 32), tb>>>(wg, wgt, DD2);

    k_chunksum<<<(BB * NCH * DD) / 256, 256>>>(inputs);
    k_scan<<<(BB * DD) / 256, 256>>>();
    k_apply<<<(BB * NCH * DD) / 256, 256>>>(inputs);
    k_ln<<<MM, 256>>>(lng, lnb);

    dim3 grid12(DD / 128, MM / 128);     // (8, 256)
    k_gemm_mma<0, DD, DD><<<grid12, 256, GEMM_SMEM>>>(h, h, w1t, b1, nullptr,
                                                      inter, nullptr);
    k_gemm_mma<1, DD, DD><<<grid12, 256, GEMM_SMEM>>>(inter, inter, w2t, b2, avg,
                                                      avgout, avgout_r);

    dim3 grid3(DD2 / 128, MM / 128);     // (16, 256)
    k_gemm_mma<2, DD2, DD2><<<grid3, 256, GEMM_SMEM>>>(in_r, avgout_r, wgt, bg,
                                                       nullptr, gates, nullptr);

    k_final<<<((size_t)MM * DD / 4) / 256, 256>>>(inputs, out);
}